// round 12
// baseline (speedup 1.0000x reference)
#include <cuda_runtime.h>
#include <math.h>

// Problem constants
#define Bv   16
#define Cv   64
#define Hv   256
#define Wv   256
#define Kv   7
#define HIDv 16
#define NCH  (Bv * Cv)          // 1024 channels
#define HWv  (Hv * Wv)          // 65536
#define KK   (Kv * Kv)          // 49
#define COLS (Cv * KK)          // 3136

// Conv tiling: persistent block over 4 vertical tiles of 128x32.
// blockDim (32,8) = 256 thr. Thread: 4 cols x 4 rows per tile.
#define TILE_W 128
#define TILE_H 32
#define NT 4
#define CPT 4
#define RPT 4
#define SROWS (TILE_H + 6)       // 38
#define SSTRIDE 136              // smem col c holds global col x0-4+c; interior c=4..131

// Scratch (no cudaMalloc allowed)
__device__ float g_pooled[NCH];
__device__ float g_wbuf[NCH * KK];

typedef unsigned long long u64;

// ---------------------------------------------------------------------------
// Packed f32x2 helpers (sm_103a)
// ---------------------------------------------------------------------------
__device__ __forceinline__ u64 pk(float lo, float hi) {
    u64 r; asm("mov.b64 %0, {%1, %2};" : "=l"(r) : "f"(lo), "f"(hi)); return r;
}
__device__ __forceinline__ u64 ffma2(u64 a, u64 b, u64 c) {
    u64 d; asm("fma.rn.f32x2 %0, %1, %2, %3;" : "=l"(d) : "l"(a), "l"(b), "l"(c)); return d;
}
__device__ __forceinline__ void up2(u64 v, float& lo, float& hi) {
    asm("mov.b64 {%0, %1}, %2;" : "=f"(lo), "=f"(hi) : "l"(v));
}

// ---------------------------------------------------------------------------
// Kernel 1: global average pool.
// ---------------------------------------------------------------------------
__global__ void gap_kernel(const float* __restrict__ x) {
    const int ch = blockIdx.x;
    const float4* p = reinterpret_cast<const float4*>(x + (size_t)ch * HWv);
    float s = 0.f;
    #pragma unroll 8
    for (int i = threadIdx.x; i < HWv / 4; i += 256) {
        float4 v = p[i];
        s += (v.x + v.y) + (v.z + v.w);
    }
    #pragma unroll
    for (int off = 16; off > 0; off >>= 1)
        s += __shfl_xor_sync(0xffffffffu, s, off);
    __shared__ float red[8];
    const int lane = threadIdx.x & 31, wid = threadIdx.x >> 5;
    if (lane == 0) red[wid] = s;
    __syncthreads();
    if (threadIdx.x == 0) {
        float t = 0.f;
        #pragma unroll
        for (int i = 0; i < 8; ++i) t += red[i];
        g_pooled[ch] = t * (1.0f / (float)HWv);
    }
}

// ---------------------------------------------------------------------------
// Kernel 2: MLP weight generator.
// ---------------------------------------------------------------------------
__global__ void mlp_kernel(const float* __restrict__ w1, const float* __restrict__ b1,
                           const float* __restrict__ w2, const float* __restrict__ b2) {
    __shared__ float sp[NCH];
    __shared__ float sh[Bv * HIDv];
    const int tid = threadIdx.x;

    for (int i = tid; i < NCH; i += 256) sp[i] = g_pooled[i];
    __syncthreads();

    {
        const int b = tid >> 4, h = tid & 15;
        float s = b1[h];
        #pragma unroll
        for (int c = 0; c < Cv; ++c)
            s = fmaf(sp[b * Cv + c], w1[c * HIDv + h], s);
        sh[tid] = 0.5f * s * (1.0f + erff(s * 0.70710678118654752f));
    }
    __syncthreads();

    const int j0 = blockIdx.x * 49;
    for (int t = tid; t < 49 * Bv; t += 256) {
        const int jl = t / 16, b = t & 15;
        const int j = j0 + jl;
        float s = b2[j];
        #pragma unroll
        for (int h = 0; h < HIDv; ++h)
            s = fmaf(sh[b * HIDv + h], w2[h * COLS + j], s);
        g_wbuf[b * COLS + j] = 1.0f / (1.0f + __expf(-s));
    }
}

__global__ void dummy_kernel() {}

// ---------------------------------------------------------------------------
// cp.async helpers + R11 vectorized tile loader (unchanged)
// ---------------------------------------------------------------------------
__device__ __forceinline__ int reflect_idx(int i) {
    return i < 0 ? -i : (i > 255 ? 510 - i : i);
}
__device__ __forceinline__ void cpasync4(float* dst_smem, const float* src_gmem) {
    unsigned dst = (unsigned)__cvta_generic_to_shared(dst_smem);
    asm volatile("cp.async.ca.shared.global [%0], [%1], 4;" :: "r"(dst), "l"(src_gmem));
}
__device__ __forceinline__ void cpasync16(float* dst_smem, const float* src_gmem) {
    unsigned dst = (unsigned)__cvta_generic_to_shared(dst_smem);
    asm volatile("cp.async.cg.shared.global [%0], [%1], 16;" :: "r"(dst), "l"(src_gmem));
}
__device__ __forceinline__ void load_tile_async(float* __restrict__ buf,
                                                const float* __restrict__ xc,
                                                int x0, int y0, int tx, int ty) {
    for (int r = ty; r < SROWS; r += 8) {
        const int gr = reflect_idx(y0 - 3 + r);
        const float* __restrict__ rowp = xc + gr * Wv;
        float* __restrict__ srow = buf + r * SSTRIDE;
        cpasync16(srow + 4 + 4 * tx, rowp + x0 + 4 * tx);
        if (tx < 6) {
            const int c = (tx < 3) ? (tx + 1) : (129 + tx);
            cpasync4(srow + c, rowp + reflect_idx(x0 - 4 + c));
        }
    }
}

// ---------------------------------------------------------------------------
// FFMA2 compute: two passes over tap rows.
//   Pass A: dy 0..3 (28 splatted weights), input rows R=0..6 (relative)
//   Pass B: dy 4..6 (21 splatted weights), input rows R=4..9
// Value pairs pr[s] = {v[s], v[s+1]}; acc[o][0]={col0,col1}, acc[o][1]={col2,col3}.
// Output col j taps value index j+1+dx.
// ---------------------------------------------------------------------------
__device__ __forceinline__ void load_pairs(const float* __restrict__ row, u64 (&pr)[10]) {
    float4 t0 = *reinterpret_cast<const float4*>(row);
    float4 t1 = *reinterpret_cast<const float4*>(row + 4);
    float4 t2 = *reinterpret_cast<const float4*>(row + 8);
    float v[12];
    v[0] = t0.x; v[1] = t0.y; v[2]  = t0.z; v[3]  = t0.w;
    v[4] = t1.x; v[5] = t1.y; v[6]  = t1.z; v[7]  = t1.w;
    v[8] = t2.x; v[9] = t2.y; v[10] = t2.z; v[11] = t2.w;
    #pragma unroll
    for (int s = 1; s <= 9; ++s) pr[s] = pk(v[s], v[s + 1]);
}

template<int R>
__device__ __forceinline__ void passA_row(const float* __restrict__ row,
                                          const u64 (&wp)[28], u64 (&acc)[RPT][2]) {
    u64 pr[10];
    load_pairs(row, pr);
    constexpr int OLO = (R > 3) ? (R - 3) : 0;
    constexpr int OHI = (R < RPT - 1) ? R : (RPT - 1);
    #pragma unroll
    for (int o = OLO; o <= OHI; ++o) {
        const int dy = R - o;                 // 0..3
        #pragma unroll
        for (int dx = 0; dx < 7; ++dx) {
            acc[o][0] = ffma2(wp[dy * 7 + dx], pr[dx + 1], acc[o][0]);
            acc[o][1] = ffma2(wp[dy * 7 + dx], pr[dx + 3], acc[o][1]);
        }
    }
}

template<int R>
__device__ __forceinline__ void passA_rows(const float* __restrict__ base,
                                           const u64 (&wp)[28], u64 (&acc)[RPT][2]) {
    passA_row<R>(base + R * SSTRIDE, wp, acc);
    if constexpr (R + 1 <= RPT + 2)          // rows 0..6
        passA_rows<R + 1>(base, wp, acc);
}

template<int R>
__device__ __forceinline__ void passB_row(const float* __restrict__ row,
                                          const u64 (&wp)[21], u64 (&acc)[RPT][2]) {
    u64 pr[10];
    load_pairs(row, pr);
    constexpr int OLO = (R > 6) ? (R - 6) : 0;
    constexpr int OHI = ((R - 4) < RPT - 1) ? (R - 4) : (RPT - 1);
    #pragma unroll
    for (int o = OLO; o <= OHI; ++o) {
        const int dy = R - o - 4;             // 0..2 (maps to taps 4..6)
        #pragma unroll
        for (int dx = 0; dx < 7; ++dx) {
            acc[o][0] = ffma2(wp[dy * 7 + dx], pr[dx + 1], acc[o][0]);
            acc[o][1] = ffma2(wp[dy * 7 + dx], pr[dx + 3], acc[o][1]);
        }
    }
}

template<int R>
__device__ __forceinline__ void passB_rows(const float* __restrict__ base,
                                           const u64 (&wp)[21], u64 (&acc)[RPT][2]) {
    passB_row<R>(base + R * SSTRIDE, wp, acc);
    if constexpr (R + 1 <= RPT + 5)          // rows 4..9
        passB_rows<R + 1>(base, wp, acc);
}

__global__ void __launch_bounds__(256, 2)
dwconv_kernel(const float* __restrict__ x, float* __restrict__ out) {
    __shared__ __align__(16) float buf0[SROWS * SSTRIDE];
    __shared__ __align__(16) float buf1[SROWS * SSTRIDE];
    __shared__ __align__(8) float2 wsh2[KK];    // splatted {w,w}

    const int ch = blockIdx.z;
    const int x0 = blockIdx.x * TILE_W;
    const int ybase = blockIdx.y * 128;
    const int tx = threadIdx.x, ty = threadIdx.y;
    const int tid = ty * 32 + tx;

    const float* __restrict__ xc = x + (size_t)ch * HWv;

    if (tid < KK) {
        const float wv = g_wbuf[ch * KK + tid];
        wsh2[tid] = make_float2(wv, wv);
    }

    load_tile_async(buf0, xc, x0, ybase, tx, ty);
    asm volatile("cp.async.commit_group;");

    const int col = tx * CPT;                // 0..124
    const int rbase = ty * RPT;              // 0..28

    #pragma unroll 1
    for (int t = 0; t < NT; ++t) {
        asm volatile("cp.async.wait_group 0;");
        __syncthreads();

        if (t + 1 < NT) {
            load_tile_async((t & 1) ? buf0 : buf1, xc, x0, ybase + (t + 1) * TILE_H, tx, ty);
            asm volatile("cp.async.commit_group;");
        }

        const float* __restrict__ cur = (t & 1) ? buf1 : buf0;
        const float* __restrict__ base = &cur[rbase * SSTRIDE + 4 * tx];

        u64 acc[RPT][2];
        #pragma unroll
        for (int o = 0; o < RPT; ++o) { acc[o][0] = 0ull; acc[o][1] = 0ull; }

        {   // Pass A: taps dy 0..3
            u64 wpA[28];
            #pragma unroll
            for (int k = 0; k < 28; ++k)
                wpA[k] = *reinterpret_cast<const u64*>(&wsh2[k]);
            passA_rows<0>(base, wpA, acc);
        }
        {   // Pass B: taps dy 4..6
            u64 wpB[21];
            #pragma unroll
            for (int k = 0; k < 21; ++k)
                wpB[k] = *reinterpret_cast<const u64*>(&wsh2[28 + k]);
            passB_rows<4>(base, wpB, acc);
        }

        const int y0 = ybase + t * TILE_H;
        float* __restrict__ oc = out + (size_t)ch * HWv + (size_t)(y0 + rbase) * Wv + x0 + col;
        #pragma unroll
        for (int o = 0; o < RPT; ++o) {
            float c0, c1, c2, c3;
            up2(acc[o][0], c0, c1);
            up2(acc[o][1], c2, c3);
            *reinterpret_cast<float4*>(oc + o * Wv) = make_float4(c0, c1, c2, c3);
        }
    }
}

// ---------------------------------------------------------------------------
extern "C" void kernel_launch(void* const* d_in, const int* in_sizes, int n_in,
                              void* d_out, int out_size) {
    const float* x  = (const float*)d_in[0];
    const float* w1 = (const float*)d_in[1];
    const float* b1 = (const float*)d_in[2];
    const float* w2 = (const float*)d_in[3];
    const float* b2 = (const float*)d_in[4];
    float* out = (float*)d_out;

    gap_kernel<<<NCH, 256>>>(x);
    mlp_kernel<<<64, 256>>>(w1, b1, w2, b2);
    dummy_kernel<<<1, 32>>>();
    dwconv_kernel<<<dim3(2, 2, NCH), dim3(32, 8)>>>(x, out);
}

// round 13
// speedup vs baseline: 1.1367x; 1.1367x over previous
#include <cuda_runtime.h>
#include <math.h>

// Problem constants
#define Bv   16
#define Cv   64
#define Hv   256
#define Wv   256
#define Kv   7
#define HIDv 16
#define NCH  (Bv * Cv)          // 1024 channels
#define HWv  (Hv * Wv)          // 65536
#define KK   (Kv * Kv)          // 49
#define COLS (Cv * KK)          // 3136

// Conv tiling: persistent block over 4 vertical tiles of 128x32.
// blockDim (32,8) = 256 thr. Thread: 4 cols x 4 rows per tile.
#define TILE_W 128
#define TILE_H 32
#define NT 4
#define CPT 4
#define RPT 4
#define IN_ROWS (RPT + 6)        // 10 input rows per thread
#define SROWS (TILE_H + 6)       // 38
#define SSTRIDE 136              // smem col c holds global col x0-4+c; interior c=4..131

// Scratch (no cudaMalloc allowed)
__device__ float g_pooled[NCH];
__device__ float g_wbuf[NCH * KK];

// ---------------------------------------------------------------------------
// Kernel 1: global average pool. One block per channel, 512 threads.
// ---------------------------------------------------------------------------
__global__ void gap_kernel(const float* __restrict__ x) {
    const int ch = blockIdx.x;
    const float4* p = reinterpret_cast<const float4*>(x + (size_t)ch * HWv);
    float s = 0.f;
    #pragma unroll 8
    for (int i = threadIdx.x; i < HWv / 4; i += 512) {
        float4 v = p[i];
        s += (v.x + v.y) + (v.z + v.w);
    }
    #pragma unroll
    for (int off = 16; off > 0; off >>= 1)
        s += __shfl_xor_sync(0xffffffffu, s, off);
    __shared__ float red[16];
    const int lane = threadIdx.x & 31, wid = threadIdx.x >> 5;
    if (lane == 0) red[wid] = s;
    __syncthreads();
    if (threadIdx.x == 0) {
        float t = 0.f;
        #pragma unroll
        for (int i = 0; i < 16; ++i) t += red[i];
        g_pooled[ch] = t * (1.0f / (float)HWv);
    }
}

// ---------------------------------------------------------------------------
// Kernel 2: MLP weight generator (tiny; 64 blocks x 256 thr).
// ---------------------------------------------------------------------------
__global__ void mlp_kernel(const float* __restrict__ w1, const float* __restrict__ b1,
                           const float* __restrict__ w2, const float* __restrict__ b2) {
    __shared__ float sp[NCH];
    __shared__ float sh[Bv * HIDv];
    const int tid = threadIdx.x;

    for (int i = tid; i < NCH; i += 256) sp[i] = g_pooled[i];
    __syncthreads();

    {
        const int b = tid >> 4, h = tid & 15;
        float s = b1[h];
        #pragma unroll
        for (int c = 0; c < Cv; ++c)
            s = fmaf(sp[b * Cv + c], w1[c * HIDv + h], s);
        sh[tid] = 0.5f * s * (1.0f + erff(s * 0.70710678118654752f));
    }
    __syncthreads();

    const int j0 = blockIdx.x * 49;
    for (int t = tid; t < 49 * Bv; t += 256) {
        const int jl = t / 16, b = t & 15;
        const int j = j0 + jl;
        float s = b2[j];
        #pragma unroll
        for (int h = 0; h < HIDv; ++h)
            s = fmaf(sh[b * HIDv + h], w2[h * COLS + j], s);
        g_wbuf[b * COLS + j] = 1.0f / (1.0f + __expf(-s));
    }
}

// ---------------------------------------------------------------------------
// cp.async helpers + vectorized tile loader (R11, proven)
// ---------------------------------------------------------------------------
__device__ __forceinline__ int reflect_idx(int i) {
    return i < 0 ? -i : (i > 255 ? 510 - i : i);
}
__device__ __forceinline__ void cpasync4(float* dst_smem, const float* src_gmem) {
    unsigned dst = (unsigned)__cvta_generic_to_shared(dst_smem);
    asm volatile("cp.async.ca.shared.global [%0], [%1], 4;" :: "r"(dst), "l"(src_gmem));
}
__device__ __forceinline__ void cpasync16(float* dst_smem, const float* src_gmem) {
    unsigned dst = (unsigned)__cvta_generic_to_shared(dst_smem);
    asm volatile("cp.async.cg.shared.global [%0], [%1], 16;" :: "r"(dst), "l"(src_gmem));
}
__device__ __forceinline__ void load_tile_async(float* __restrict__ buf,
                                                const float* __restrict__ xc,
                                                int x0, int y0, int tx, int ty) {
    for (int r = ty; r < SROWS; r += 8) {
        const int gr = reflect_idx(y0 - 3 + r);
        const float* __restrict__ rowp = xc + gr * Wv;
        float* __restrict__ srow = buf + r * SSTRIDE;
        cpasync16(srow + 4 + 4 * tx, rowp + x0 + 4 * tx);
        if (tx < 6) {
            const int c = (tx < 3) ? (tx + 1) : (129 + tx);
            cpasync4(srow + c, rowp + reflect_idx(x0 - 4 + c));
        }
    }
}

// ---------------------------------------------------------------------------
// Kernel 3: depthwise 7x7 conv, reflect padding. R11 verbatim (FP32 FMA floor).
// ---------------------------------------------------------------------------
template<int R>
__device__ __forceinline__ void conv_row_step(const float* __restrict__ row,
                                              const float (&w)[KK],
                                              float4 (&acc)[RPT]) {
    float v[12];
    {
        float4 t0 = *reinterpret_cast<const float4*>(row);
        float4 t1 = *reinterpret_cast<const float4*>(row + 4);
        float4 t2 = *reinterpret_cast<const float4*>(row + 8);
        v[0] = t0.x; v[1] = t0.y; v[2]  = t0.z; v[3]  = t0.w;
        v[4] = t1.x; v[5] = t1.y; v[6]  = t1.z; v[7]  = t1.w;
        v[8] = t2.x; v[9] = t2.y; v[10] = t2.z; v[11] = t2.w;
    }
    constexpr int OLO = (R > 6) ? (R - 6) : 0;
    constexpr int OHI = (R < RPT - 1) ? R : (RPT - 1);
    #pragma unroll
    for (int o = OLO; o <= OHI; ++o) {
        const int dy = R - o;
        #pragma unroll
        for (int dx = 0; dx < 7; ++dx) {
            const float wv = w[dy * 7 + dx];
            acc[o].x = fmaf(wv, v[dx + 1], acc[o].x);
            acc[o].y = fmaf(wv, v[dx + 2], acc[o].y);
            acc[o].z = fmaf(wv, v[dx + 3], acc[o].z);
            acc[o].w = fmaf(wv, v[dx + 4], acc[o].w);
        }
    }
}

template<int R>
__device__ __forceinline__ void conv_rows(const float* __restrict__ base,
                                          const float (&w)[KK],
                                          float4 (&acc)[RPT]) {
    conv_row_step<R>(base + R * SSTRIDE, w, acc);
    if constexpr (R + 1 < IN_ROWS)
        conv_rows<R + 1>(base, w, acc);
}

__global__ void __launch_bounds__(256, 2)
dwconv_kernel(const float* __restrict__ x, float* __restrict__ out) {
    __shared__ __align__(16) float buf0[SROWS * SSTRIDE];
    __shared__ __align__(16) float buf1[SROWS * SSTRIDE];
    __shared__ float wsh[KK];

    const int ch = blockIdx.z;
    const int x0 = blockIdx.x * TILE_W;      // 0 or 128
    const int ybase = blockIdx.y * 128;      // 0 or 128
    const int tx = threadIdx.x, ty = threadIdx.y;
    const int tid = ty * 32 + tx;

    const float* __restrict__ xc = x + (size_t)ch * HWv;

    if (tid < KK) wsh[tid] = g_wbuf[ch * KK + tid];

    // Prologue: stream tile 0 into buf0.
    load_tile_async(buf0, xc, x0, ybase, tx, ty);
    asm volatile("cp.async.commit_group;");

    float w[KK];
    const int col = tx * CPT;                // 0..124
    const int rbase = ty * RPT;              // 0..28

    #pragma unroll 1
    for (int t = 0; t < NT; ++t) {
        asm volatile("cp.async.wait_group 0;");
        __syncthreads();

        if (t == 0) {
            #pragma unroll
            for (int k = 0; k < KK; ++k) w[k] = wsh[k];
        }

        // Stream next tile into the other buffer while computing this one.
        if (t + 1 < NT) {
            load_tile_async((t & 1) ? buf0 : buf1, xc, x0, ybase + (t + 1) * TILE_H, tx, ty);
            asm volatile("cp.async.commit_group;");
        }

        const float* __restrict__ cur = (t & 1) ? buf1 : buf0;

        float4 acc[RPT];
        #pragma unroll
        for (int o = 0; o < RPT; ++o) acc[o] = make_float4(0.f, 0.f, 0.f, 0.f);

        conv_rows<0>(&cur[rbase * SSTRIDE + col], w, acc);

        const int y0 = ybase + t * TILE_H;
        float* __restrict__ oc = out + (size_t)ch * HWv + (size_t)(y0 + rbase) * Wv + x0 + col;
        #pragma unroll
        for (int o = 0; o < RPT; ++o)
            *reinterpret_cast<float4*>(oc + o * Wv) = acc[o];
    }
}

// ---------------------------------------------------------------------------
extern "C" void kernel_launch(void* const* d_in, const int* in_sizes, int n_in,
                              void* d_out, int out_size) {
    const float* x  = (const float*)d_in[0];
    const float* w1 = (const float*)d_in[1];
    const float* b1 = (const float*)d_in[2];
    const float* w2 = (const float*)d_in[3];
    const float* b2 = (const float*)d_in[4];
    float* out = (float*)d_out;

    gap_kernel<<<NCH, 512>>>(x);
    mlp_kernel<<<64, 256>>>(w1, b1, w2, b2);
    dwconv_kernel<<<dim3(2, 2, NCH), dim3(32, 8)>>>(x, out);
}